// round 15
// baseline (speedup 1.0000x reference)
#include <cuda_runtime.h>

// Problem constants (fixed by the dataset: pcd [8, 4096, 3] fp32, k = 5)
#define NB 8
#define NPTS 4096
#define KNN 5
#define GDIM 16
#define GC (GDIM * GDIM * GDIM)    // 4096 cells
#define QTPB 128

typedef unsigned long long u64;

// Scratch (allocation-free rule -> __device__ globals)
__device__ float4 g_pts[NB * NPTS];      // cell-sorted: x, y, z, |p|^2
__device__ int    g_orig[NB * NPTS];     // original index per sorted slot
__device__ int    g_bst[NB * (GC + 1)];  // cell start offsets (+ total)
__device__ float  g_bbox[NB][8];         // minx,miny,minz, invwx,invwy,invwz
__device__ float  g_partial[NB * 16];    // per-psum-CTA trace partial sums

// --------------------------------------------------------------------------
// K1 (fused build, 1 CTA per batch, 1024 thr): bbox -> 4096-cell histogram
// -> exclusive scan -> scatter into cell-sorted arrays.
// Cell formula must match the query kernel exactly (same ops, same clamps).
// --------------------------------------------------------------------------
__global__ __launch_bounds__(1024) void build_kernel(const float* __restrict__ pcd)
{
    __shared__ float sred[6][32];
    __shared__ float sbb[6];
    __shared__ int   scnt[GC];      // 16 KB
    __shared__ int   scur[GC];      // 16 KB
    __shared__ int   swsum[32];

    const int b = blockIdx.x;
    const float* base = pcd + (size_t)b * NPTS * 3;
    const int tid = threadIdx.x;
    const int lane = tid & 31, wid = tid >> 5;

    float mnx = 1e30f, mny = 1e30f, mnz = 1e30f;
    float mxx = -1e30f, mxy = -1e30f, mxz = -1e30f;
    for (int i = tid; i < NPTS; i += 1024) {
        float x = base[i * 3 + 0], y = base[i * 3 + 1], z = base[i * 3 + 2];
        mnx = fminf(mnx, x); mny = fminf(mny, y); mnz = fminf(mnz, z);
        mxx = fmaxf(mxx, x); mxy = fmaxf(mxy, y); mxz = fmaxf(mxz, z);
    }
#pragma unroll
    for (int off = 16; off; off >>= 1) {
        mnx = fminf(mnx, __shfl_xor_sync(0xffffffffu, mnx, off));
        mny = fminf(mny, __shfl_xor_sync(0xffffffffu, mny, off));
        mnz = fminf(mnz, __shfl_xor_sync(0xffffffffu, mnz, off));
        mxx = fmaxf(mxx, __shfl_xor_sync(0xffffffffu, mxx, off));
        mxy = fmaxf(mxy, __shfl_xor_sync(0xffffffffu, mxy, off));
        mxz = fmaxf(mxz, __shfl_xor_sync(0xffffffffu, mxz, off));
    }
    if (lane == 0) {
        sred[0][wid] = mnx; sred[1][wid] = mny; sred[2][wid] = mnz;
        sred[3][wid] = mxx; sred[4][wid] = mxy; sred[5][wid] = mxz;
    }
    __syncthreads();
    if (tid == 0) {
        float a0 = sred[0][0], a1 = sred[1][0], a2 = sred[2][0];
        float a3 = sred[3][0], a4 = sred[4][0], a5 = sred[5][0];
        for (int w = 1; w < 32; w++) {
            a0 = fminf(a0, sred[0][w]); a1 = fminf(a1, sred[1][w]); a2 = fminf(a2, sred[2][w]);
            a3 = fmaxf(a3, sred[3][w]); a4 = fmaxf(a4, sred[4][w]); a5 = fmaxf(a5, sred[5][w]);
        }
        float ex = (a3 - a0) + 1e-5f;
        float ey = (a4 - a1) + 1e-5f;
        float ez = (a5 - a2) + 1e-5f;
        sbb[0] = a0; sbb[1] = a1; sbb[2] = a2;
        sbb[3] = (float)GDIM / ex;
        sbb[4] = (float)GDIM / ey;
        sbb[5] = (float)GDIM / ez;
        g_bbox[b][0] = a0; g_bbox[b][1] = a1; g_bbox[b][2] = a2;
        g_bbox[b][3] = sbb[3]; g_bbox[b][4] = sbb[4]; g_bbox[b][5] = sbb[5];
    }
    for (int i = tid; i < GC; i += 1024) scnt[i] = 0;
    __syncthreads();

    const float bx = sbb[0], by = sbb[1], bz = sbb[2];
    const float ix = sbb[3], iy = sbb[4], iz = sbb[5];

    for (int i = tid; i < NPTS; i += 1024) {
        float x = base[i * 3 + 0], y = base[i * 3 + 1], z = base[i * 3 + 2];
        int cx = min(GDIM - 1, max(0, (int)((x - bx) * ix)));
        int cy = min(GDIM - 1, max(0, (int)((y - by) * iy)));
        int cz = min(GDIM - 1, max(0, (int)((z - bz) * iz)));
        atomicAdd(&scnt[(cz * GDIM + cy) * GDIM + cx], 1);
    }
    __syncthreads();

    const int c0 = tid * 4;
    int T = scnt[c0] + scnt[c0 + 1] + scnt[c0 + 2] + scnt[c0 + 3];
    int incl = T;
#pragma unroll
    for (int off = 1; off < 32; off <<= 1) {
        int n = __shfl_up_sync(0xffffffffu, incl, off);
        if (lane >= off) incl += n;
    }
    if (lane == 31) swsum[wid] = incl;
    __syncthreads();
    if (wid == 0) {
        int v = swsum[lane];
        int iv = v;
#pragma unroll
        for (int off = 1; off < 32; off <<= 1) {
            int n = __shfl_up_sync(0xffffffffu, iv, off);
            if (lane >= off) iv += n;
        }
        swsum[lane] = iv - v;
    }
    __syncthreads();
    {
        int run = swsum[wid] + (incl - T);
#pragma unroll
        for (int i = 0; i < 4; i++) {
            int c = scnt[c0 + i];
            scur[c0 + i] = run;
            g_bst[b * (GC + 1) + c0 + i] = run;
            run += c;
        }
        if (tid == 0) g_bst[b * (GC + 1) + GC] = NPTS;
    }
    __syncthreads();

    for (int i = tid; i < NPTS; i += 1024) {
        float x = base[i * 3 + 0], y = base[i * 3 + 1], z = base[i * 3 + 2];
        int cx = min(GDIM - 1, max(0, (int)((x - bx) * ix)));
        int cy = min(GDIM - 1, max(0, (int)((y - by) * iy)));
        int cz = min(GDIM - 1, max(0, (int)((z - bz) * iz)));
        int pos = atomicAdd(&scur[(cz * GDIM + cy) * GDIM + cx], 1);
        g_pts[b * NPTS + pos] = make_float4(x, y, z, fmaf(x, x, fmaf(y, y, z * z)));
        g_orig[b * NPTS + pos] = i;
    }
}

// --------------------------------------------------------------------------
// K2 (query): WARP-UNIFORM expanding-box exact kNN. The warp's 32 queries
// (cell-sorted slots) share one scan box = union of lanes' cell neighborhoods
// (warp-reduced). All run bounds and LDS addresses are warp-uniform
// (broadcast); each lane keeps its own exact top-5.
// cand = (bits(max(d2,0)) << 32) | orig -> u64 '<' == top_k order exactly.
// Per-lane stop: 5th distance^2 <= (distance to nearest non-domain-edge box
// face)^2 with conservative margins; warp expands the box while any lane
// still needs more. Over-scan is harmless; bounds never under-scan.
// --------------------------------------------------------------------------
__global__ __launch_bounds__(QTPB) void query_kernel(
    const float* __restrict__ pcd, float* __restrict__ out)
{
    extern __shared__ char smem[];
    float4* sp  = (float4*)smem;                               // 64 KB
    int*    sor = (int*)(smem + NPTS * 16);                    // 16 KB
    int*    sst = (int*)(smem + NPTS * 16 + NPTS * 4);         // (GC+1)*4 B

    const int b = blockIdx.x >> 5;                      // 32 CTAs per batch
    const int t = (blockIdx.x & 31) * QTPB + threadIdx.x;  // sorted slot

    for (int i = threadIdx.x; i < NPTS; i += QTPB) {
        sp[i]  = g_pts[b * NPTS + i];
        sor[i] = g_orig[b * NPTS + i];
    }
    for (int i = threadIdx.x; i <= GC; i += QTPB)
        sst[i] = g_bst[b * (GC + 1) + i];
    __syncthreads();

    const float bx = g_bbox[b][0], by = g_bbox[b][1], bz = g_bbox[b][2];
    const float ix = g_bbox[b][3], iy = g_bbox[b][4], iz = g_bbox[b][5];
    const float wx = 1.0f / ix, wy = 1.0f / iy, wz = 1.0f / iz;

    const float4 q = sp[t];
    const float nx = -2.0f * q.x, ny = -2.0f * q.y, nz = -2.0f * q.z;
    const float q2 = q.w;

    const int cx = min(GDIM - 1, max(0, (int)((q.x - bx) * ix)));
    const int cy = min(GDIM - 1, max(0, (int)((q.y - by) * iy)));
    const int cz = min(GDIM - 1, max(0, (int)((q.z - bz) * iz)));

    // Warp-shared box: union of all lanes' (cell +- 1) neighborhoods.
    int bx0 = max((int)__reduce_min_sync(0xffffffffu, (unsigned)cx) - 1, 0);
    int bx1 = min((int)__reduce_max_sync(0xffffffffu, (unsigned)cx) + 1, GDIM - 1);
    int by0 = max((int)__reduce_min_sync(0xffffffffu, (unsigned)cy) - 1, 0);
    int by1 = min((int)__reduce_max_sync(0xffffffffu, (unsigned)cy) + 1, GDIM - 1);
    int bz0 = max((int)__reduce_min_sync(0xffffffffu, (unsigned)cz) - 1, 0);
    int bz1 = min((int)__reduce_max_sync(0xffffffffu, (unsigned)cz) + 1, GDIM - 1);

    u64 h0 = ~0ull, h1 = ~0ull, h2 = ~0ull, h3 = ~0ull, h4 = ~0ull;

    // One x-contiguous run of cells [X0..X1] at fixed (Y,Z); bounds uniform.
    // Branchless exact insert (at these candidate counts nearly every point
    // inserts for some lane; branchless also avoids BSSY/BSYNC).
#define PROCR(X0, X1, Y, Z)                                                   \
    {                                                                         \
        const int cid0 = ((Z) * GDIM + (Y)) * GDIM + (X0);                    \
        const int cs = sst[cid0];                                             \
        const int ce = sst[cid0 + ((X1) - (X0)) + 1];                         \
        for (int i = cs; i < ce; i++) {                                       \
            float4 p = sp[i];                                                 \
            float key = fmaxf(                                                \
                fmaf(p.x, nx, fmaf(p.y, ny, fmaf(p.z, nz, p.w + q2))), 0.0f); \
            u64 cand = ((u64)__float_as_uint(key) << 32) | (unsigned)sor[i];  \
            bool l0 = cand < h0, l1 = cand < h1, l2 = cand < h2,              \
                 l3 = cand < h3, l4 = cand < h4;                              \
            h4 = l4 ? (l3 ? h3 : cand) : h4;                                  \
            h3 = l3 ? (l2 ? h2 : cand) : h3;                                  \
            h2 = l2 ? (l1 ? h1 : cand) : h2;                                  \
            h1 = l1 ? (l0 ? h0 : cand) : h1;                                  \
            h0 = l0 ? cand : h0;                                              \
        }                                                                     \
    }

    // Initial box sweep.
    for (int z = bz0; z <= bz1; z++)
        for (int y = by0; y <= by1; y++)
            PROCR(bx0, bx1, y, z);

    // Expand while any lane's bound is unproven.
    for (int iter = 0; iter < GDIM; iter++) {
        const float k5f = __uint_as_float((unsigned)(h4 >> 32)); // NaN until 5 found
        float m = 1e30f;
        if (bx0 > 0)        m = fminf(m, q.x - (bx + (float)bx0 * wx));
        if (bx1 < GDIM - 1) m = fminf(m, (bx + (float)(bx1 + 1) * wx) - q.x);
        if (by0 > 0)        m = fminf(m, q.y - (by + (float)by0 * wy));
        if (by1 < GDIM - 1) m = fminf(m, (by + (float)(by1 + 1) * wy) - q.y);
        if (bz0 > 0)        m = fminf(m, q.z - (bz + (float)bz0 * wz));
        if (bz1 < GDIM - 1) m = fminf(m, (bz + (float)(bz1 + 1) * wz) - q.z);
        m = fmaxf(m - 1e-4f, 0.0f);
        const bool done = (k5f <= m * m * 0.999f);   // NaN-safe: false
        if (__all_sync(0xffffffffu, done)) break;

        const int nx0 = max(bx0 - 1, 0), nx1 = min(bx1 + 1, GDIM - 1);
        const int ny0 = max(by0 - 1, 0), ny1 = min(by1 + 1, GDIM - 1);
        const int nz0 = max(bz0 - 1, 0), nz1 = min(bz1 + 1, GDIM - 1);
        // New z slabs (full new-box xy extent).
        if (nz0 < bz0)
            for (int y = ny0; y <= ny1; y++) PROCR(nx0, nx1, y, nz0);
        if (nz1 > bz1)
            for (int y = ny0; y <= ny1; y++) PROCR(nx0, nx1, y, nz1);
        // Middle z: new y rows (full new-box x extent) and new x columns.
        for (int z = bz0; z <= bz1; z++) {
            if (ny0 < by0) PROCR(nx0, nx1, ny0, z);
            if (ny1 > by1) PROCR(nx0, nx1, ny1, z);
            for (int y = by0; y <= by1; y++) {
                if (nx0 < bx0) PROCR(nx0, nx0, y, z);
                if (nx1 > bx1) PROCR(nx1, nx1, y, z);
            }
        }
        bx0 = nx0; bx1 = nx1; by0 = ny0; by1 = ny1; bz0 = nz0; bz1 = nz1;
    }
#undef PROCR

    // Gather the 5 neighbors by original index; reference numerics.
    const float* basep = pcd + (size_t)b * NPTS * 3;
    const unsigned id0 = (unsigned)h0, id1 = (unsigned)h1, id2 = (unsigned)h2,
                   id3 = (unsigned)h3, id4 = (unsigned)h4;
    float px[KNN], py[KNN], pz[KNN];
    px[0] = basep[id0 * 3 + 0]; py[0] = basep[id0 * 3 + 1]; pz[0] = basep[id0 * 3 + 2];
    px[1] = basep[id1 * 3 + 0]; py[1] = basep[id1 * 3 + 1]; pz[1] = basep[id1 * 3 + 2];
    px[2] = basep[id2 * 3 + 0]; py[2] = basep[id2 * 3 + 1]; pz[2] = basep[id2 * 3 + 2];
    px[3] = basep[id3 * 3 + 0]; py[3] = basep[id3 * 3 + 1]; pz[3] = basep[id3 * 3 + 2];
    px[4] = basep[id4 * 3 + 0]; py[4] = basep[id4 * 3 + 1]; pz[4] = basep[id4 * 3 + 2];

    const float inv_k = 1.0f / (float)KNN;
    float mx = (px[0] + px[1] + px[2] + px[3] + px[4]) * inv_k;
    float my = (py[0] + py[1] + py[2] + py[3] + py[4]) * inv_k;
    float mz = (pz[0] + pz[1] + pz[2] + pz[3] + pz[4]) * inv_k;

    float tr = 0.0f;
#pragma unroll
    for (int c = 0; c < KNN; c++) {
        float dx = px[c] - mx, dy = py[c] - my, dz = pz[c] - mz;
        tr = fmaf(dx, dx, fmaf(dy, dy, fmaf(dz, dz, tr)));
    }
    tr *= 1.0f / (float)(KNN - 1);
    out[b * NPTS + sor[t]] = tr;
}

// --------------------------------------------------------------------------
// K3: deterministic per-CTA partial sums of traces (original index order).
// --------------------------------------------------------------------------
__global__ __launch_bounds__(256) void psum_kernel(const float* __restrict__ out)
{
    __shared__ float warp_sums[8];
    const int t = blockIdx.x * 256 + threadIdx.x;
    float s = out[t];
#pragma unroll
    for (int off = 16; off > 0; off >>= 1)
        s += __shfl_down_sync(0xffffffffu, s, off);
    if ((threadIdx.x & 31) == 0) warp_sums[threadIdx.x >> 5] = s;
    __syncthreads();
    if (threadIdx.x < 32) {
        float v = (threadIdx.x < 8) ? warp_sums[threadIdx.x] : 0.0f;
#pragma unroll
        for (int off = 4; off > 0; off >>= 1)
            v += __shfl_down_sync(0xffffffffu, v, off);
        if (threadIdx.x == 0) g_partial[blockIdx.x] = v;
    }
}

// --------------------------------------------------------------------------
// K4: normalize. 4 CTAs per batch; each redundantly sums its batch's 16
// partials with a fixed-order tree (deterministic) and scales its quarter.
// --------------------------------------------------------------------------
__global__ __launch_bounds__(256) void finalize_kernel(float* __restrict__ out)
{
    __shared__ float s_inv;
    const int b = blockIdx.x >> 2;
    const int quarter = blockIdx.x & 3;

    if (threadIdx.x < 32) {
        float v = (threadIdx.x < 16) ? g_partial[b * 16 + threadIdx.x] : 0.0f;
#pragma unroll
        for (int off = 8; off > 0; off >>= 1)
            v += __shfl_down_sync(0xffffffffu, v, off);
        if (threadIdx.x == 0) s_inv = 1.0f / (v + 1e-8f);
    }
    __syncthreads();

    const float inv = s_inv;
    float* o = out + (size_t)b * NPTS + quarter * (NPTS / 4);
#pragma unroll
    for (int i = 0; i < (NPTS / 4) / 256; i++)
        o[i * 256 + threadIdx.x] *= inv;
}

extern "C" void kernel_launch(void* const* d_in, const int* in_sizes, int n_in,
                              void* d_out, int out_size)
{
    const float* pcd = (const float*)d_in[0];
    float* out = (float*)d_out;

    static bool attr_set = false;  // idempotent host-side attribute
    const int smemq = NPTS * 16 + NPTS * 4 + (GC + 1) * 4;   // ~96.4 KB
    if (!attr_set) {
        cudaFuncSetAttribute(query_kernel,
                             cudaFuncAttributeMaxDynamicSharedMemorySize, smemq);
        attr_set = true;
    }

    build_kernel<<<NB, 1024>>>(pcd);
    query_kernel<<<NB * 32, QTPB, smemq>>>(pcd, out);
    psum_kernel<<<(NB * NPTS) / 256, 256>>>(out);
    finalize_kernel<<<NB * 4, 256>>>(out);
}

// round 17
// speedup vs baseline: 1.0214x; 1.0214x over previous
#include <cuda_runtime.h>

// Problem constants (fixed by the dataset: pcd [8, 4096, 3] fp32, k = 5)
#define NB 8
#define NPTS 4096
#define KNN 5
#define GDIM 8
#define GC (GDIM * GDIM * GDIM)    // 512 cells, ~8 pts/cell
#define QTPB 128

typedef unsigned long long u64;

// Morton id for 3-bit coords (compact 3D blocks for consecutive ids).
__device__ __forceinline__ int mort3(int x, int y, int z) {
    int sx = (x & 1) | ((x & 2) << 2) | ((x & 4) << 4);
    int sy = (y & 1) | ((y & 2) << 2) | ((y & 4) << 4);
    int sz = (z & 1) | ((z & 2) << 2) | ((z & 4) << 4);
    return sx | (sy << 1) | (sz << 2);
}

// Scratch (allocation-free rule -> __device__ globals)
__device__ float4 g_pts[NB * NPTS];      // Morton-cell-sorted: x, y, z, idx-bits
__device__ int    g_bst[NB * (GC + 1)];  // cell start offsets (+ total)
__device__ float  g_bbox[NB][8];         // minx,miny,minz, invwx,invwy,invwz
__device__ float  g_partial[NB * 16];    // per-psum-CTA trace partial sums

// --------------------------------------------------------------------------
// K1 (fused build, 1 CTA per batch, 1024 thr): bbox -> 512-cell histogram
// (Morton ids) -> exclusive scan -> scatter. Cell formula identical in K2.
// --------------------------------------------------------------------------
__global__ __launch_bounds__(1024) void build_kernel(const float* __restrict__ pcd)
{
    __shared__ float sred[6][32];
    __shared__ float sbb[6];
    __shared__ int   scnt[GC];
    __shared__ int   scur[GC];
    __shared__ int   swsum[16];

    const int b = blockIdx.x;
    const float* base = pcd + (size_t)b * NPTS * 3;
    const int tid = threadIdx.x;
    const int lane = tid & 31, wid = tid >> 5;

    float mnx = 1e30f, mny = 1e30f, mnz = 1e30f;
    float mxx = -1e30f, mxy = -1e30f, mxz = -1e30f;
    for (int i = tid; i < NPTS; i += 1024) {
        float x = base[i * 3 + 0], y = base[i * 3 + 1], z = base[i * 3 + 2];
        mnx = fminf(mnx, x); mny = fminf(mny, y); mnz = fminf(mnz, z);
        mxx = fmaxf(mxx, x); mxy = fmaxf(mxy, y); mxz = fmaxf(mxz, z);
    }
#pragma unroll
    for (int off = 16; off; off >>= 1) {
        mnx = fminf(mnx, __shfl_xor_sync(0xffffffffu, mnx, off));
        mny = fminf(mny, __shfl_xor_sync(0xffffffffu, mny, off));
        mnz = fminf(mnz, __shfl_xor_sync(0xffffffffu, mnz, off));
        mxx = fmaxf(mxx, __shfl_xor_sync(0xffffffffu, mxx, off));
        mxy = fmaxf(mxy, __shfl_xor_sync(0xffffffffu, mxy, off));
        mxz = fmaxf(mxz, __shfl_xor_sync(0xffffffffu, mxz, off));
    }
    if (lane == 0) {
        sred[0][wid] = mnx; sred[1][wid] = mny; sred[2][wid] = mnz;
        sred[3][wid] = mxx; sred[4][wid] = mxy; sred[5][wid] = mxz;
    }
    __syncthreads();
    if (tid == 0) {
        float a0 = sred[0][0], a1 = sred[1][0], a2 = sred[2][0];
        float a3 = sred[3][0], a4 = sred[4][0], a5 = sred[5][0];
        for (int w = 1; w < 32; w++) {
            a0 = fminf(a0, sred[0][w]); a1 = fminf(a1, sred[1][w]); a2 = fminf(a2, sred[2][w]);
            a3 = fmaxf(a3, sred[3][w]); a4 = fmaxf(a4, sred[4][w]); a5 = fmaxf(a5, sred[5][w]);
        }
        float ex = (a3 - a0) + 1e-5f;
        float ey = (a4 - a1) + 1e-5f;
        float ez = (a5 - a2) + 1e-5f;
        sbb[0] = a0; sbb[1] = a1; sbb[2] = a2;
        sbb[3] = (float)GDIM / ex;
        sbb[4] = (float)GDIM / ey;
        sbb[5] = (float)GDIM / ez;
        g_bbox[b][0] = a0; g_bbox[b][1] = a1; g_bbox[b][2] = a2;
        g_bbox[b][3] = sbb[3]; g_bbox[b][4] = sbb[4]; g_bbox[b][5] = sbb[5];
    }
    if (tid < GC) scnt[tid] = 0;
    __syncthreads();

    const float bx = sbb[0], by = sbb[1], bz = sbb[2];
    const float ix = sbb[3], iy = sbb[4], iz = sbb[5];

    for (int i = tid; i < NPTS; i += 1024) {
        float x = base[i * 3 + 0], y = base[i * 3 + 1], z = base[i * 3 + 2];
        int cx = min(GDIM - 1, max(0, (int)((x - bx) * ix)));
        int cy = min(GDIM - 1, max(0, (int)((y - by) * iy)));
        int cz = min(GDIM - 1, max(0, (int)((z - bz) * iz)));
        atomicAdd(&scnt[mort3(cx, cy, cz)], 1);
    }
    __syncthreads();

    // Exclusive scan of 512 counts: warps 0-15, one cell per thread.
    if (tid < GC) {
        int v = scnt[tid];
        int incl = v;
#pragma unroll
        for (int off = 1; off < 32; off <<= 1) {
            int n = __shfl_up_sync(0xffffffffu, incl, off);
            if (lane >= off) incl += n;
        }
        if (lane == 31) swsum[tid >> 5] = incl;
        // stash inclusive-minus-v (exclusive within warp) in scur temporarily
        scur[tid] = incl - v;
    }
    __syncthreads();
    if (tid < 16) {
        int wv = swsum[tid];
        int wi = wv;
#pragma unroll
        for (int off = 1; off < 16; off <<= 1) {
            int n = __shfl_up_sync(0x0000ffffu, wi, off);
            if (tid >= off) wi += n;
        }
        swsum[tid] = wi - wv;
    }
    __syncthreads();
    if (tid < GC) {
        int ex0 = scur[tid] + swsum[tid >> 5];
        scur[tid] = ex0;
        g_bst[b * (GC + 1) + tid] = ex0;
        if (tid == 0) g_bst[b * (GC + 1) + GC] = NPTS;
    }
    __syncthreads();

    for (int i = tid; i < NPTS; i += 1024) {
        float x = base[i * 3 + 0], y = base[i * 3 + 1], z = base[i * 3 + 2];
        int cx = min(GDIM - 1, max(0, (int)((x - bx) * ix)));
        int cy = min(GDIM - 1, max(0, (int)((y - by) * iy)));
        int cz = min(GDIM - 1, max(0, (int)((z - bz) * iz)));
        int pos = atomicAdd(&scur[mort3(cx, cy, cz)], 1);
        g_pts[b * NPTS + pos] = make_float4(x, y, z, __int_as_float(i));
    }
}

// --------------------------------------------------------------------------
// K2 (query): warp-uniform expanding-box exact kNN over Morton cells.
// Warp = 32 consecutive Morton-sorted queries (compact cell block); box =
// union of lane cells +-1, warp-reduced -> uniform cell loop, broadcast LDS.
// Hot path: LDS.128 + 6 arith + 1 FSETP + rare branch. Inside the branch:
// exact u64 (d2bits<<32)|idx sorted insert == top_k order (smaller distance
// first, lowest index on ties), immune to scatter-order nondeterminism.
// Per-lane stop: 5th d2 <= (margin to nearest non-domain-edge box face)^2
// with conservative slack; warp expands box by 1 while any lane unproven.
// --------------------------------------------------------------------------
__global__ __launch_bounds__(QTPB) void query_kernel(
    const float* __restrict__ pcd, float* __restrict__ out)
{
    extern __shared__ char smem[];
    float4* sp  = (float4*)smem;                       // 64 KB
    int*    sst = (int*)(smem + NPTS * 16);            // (GC+1)*4 = 2052 B

    const int b = blockIdx.x >> 5;                     // 32 CTAs per batch
    const int t = (blockIdx.x & 31) * QTPB + threadIdx.x;  // sorted slot

    for (int i = threadIdx.x; i < NPTS; i += QTPB)
        sp[i] = g_pts[b * NPTS + i];
    for (int i = threadIdx.x; i <= GC; i += QTPB)
        sst[i] = g_bst[b * (GC + 1) + i];
    __syncthreads();

    const float bx = g_bbox[b][0], by = g_bbox[b][1], bz = g_bbox[b][2];
    const float ix = g_bbox[b][3], iy = g_bbox[b][4], iz = g_bbox[b][5];
    const float wxc = 1.0f / ix, wyc = 1.0f / iy, wzc = 1.0f / iz;

    const float4 q = sp[t];
    const int oi = __float_as_int(q.w);                // my original index

    const int cx = min(GDIM - 1, max(0, (int)((q.x - bx) * ix)));
    const int cy = min(GDIM - 1, max(0, (int)((q.y - by) * iy)));
    const int cz = min(GDIM - 1, max(0, (int)((q.z - bz) * iz)));

    int bx0 = max((int)__reduce_min_sync(0xffffffffu, (unsigned)cx) - 1, 0);
    int bx1 = min((int)__reduce_max_sync(0xffffffffu, (unsigned)cx) + 1, GDIM - 1);
    int by0 = max((int)__reduce_min_sync(0xffffffffu, (unsigned)cy) - 1, 0);
    int by1 = min((int)__reduce_max_sync(0xffffffffu, (unsigned)cy) + 1, GDIM - 1);
    int bz0 = max((int)__reduce_min_sync(0xffffffffu, (unsigned)cz) - 1, 0);
    int bz1 = min((int)__reduce_max_sync(0xffffffffu, (unsigned)cz) + 1, GDIM - 1);

    // +inf-keyed sentinels (NOT NaN) so the f32 guard admits from empty.
    const u64 SENT = ((u64)0x7F800000u << 32) | 0xFFFFFFFFu;
    u64 h0 = SENT, h1 = SENT, h2 = SENT, h3 = SENT, h4 = SENT;
    float k4f = __uint_as_float(0x7F800000u);          // +inf

#define PROCCELL(X, Y, Z)                                                     \
    {                                                                         \
        const int mid = mort3((X), (Y), (Z));                                 \
        const int cs = sst[mid];                                              \
        const int ce = sst[mid + 1];                                          \
        for (int i = cs; i < ce; i++) {                                       \
            float4 p = sp[i];                                                 \
            float dx = p.x - q.x, dy = p.y - q.y, dz = p.z - q.z;             \
            float kf = fmaf(dx, dx, fmaf(dy, dy, dz * dz));                   \
            if (kf <= k4f) {                                                  \
                u64 cand = ((u64)__float_as_uint(kf) << 32)                   \
                           | (unsigned)__float_as_int(p.w);                   \
                if (cand < h4) {                                              \
                    bool l0 = cand < h0, l1 = cand < h1,                      \
                         l2 = cand < h2, l3 = cand < h3;                      \
                    h4 = l3 ? h3 : cand;                                      \
                    if (l3) { h3 = l2 ? h2 : cand;                            \
                    if (l2) { h2 = l1 ? h1 : cand;                            \
                    if (l1) { h1 = l0 ? h0 : cand;                            \
                    if (l0) { h0 = cand; } } } }                              \
                    k4f = __uint_as_float((unsigned)(h4 >> 32));              \
                }                                                             \
            }                                                                 \
        }                                                                     \
    }

    // Initial box sweep.
    for (int z = bz0; z <= bz1; z++)
        for (int y = by0; y <= by1; y++)
            for (int x = bx0; x <= bx1; x++)
                PROCCELL(x, y, z);

    // Expand while any lane's bound is unproven.
    for (int iter = 0; iter < GDIM; iter++) {
        const float k5f = __uint_as_float((unsigned)(h4 >> 32));
        float m = 1e30f;
        if (bx0 > 0)        m = fminf(m, q.x - (bx + (float)bx0 * wxc));
        if (bx1 < GDIM - 1) m = fminf(m, (bx + (float)(bx1 + 1) * wxc) - q.x);
        if (by0 > 0)        m = fminf(m, q.y - (by + (float)by0 * wyc));
        if (by1 < GDIM - 1) m = fminf(m, (by + (float)(by1 + 1) * wyc) - q.y);
        if (bz0 > 0)        m = fminf(m, q.z - (bz + (float)bz0 * wzc));
        if (bz1 < GDIM - 1) m = fminf(m, (bz + (float)(bz1 + 1) * wzc) - q.z);
        m = fmaxf(m - 1e-4f, 0.0f);
        const bool done = (k5f <= m * m * 0.999f);     // +inf k5 -> false
        if (__all_sync(0xffffffffu, done)) break;

        const int nx0 = max(bx0 - 1, 0), nx1 = min(bx1 + 1, GDIM - 1);
        const int ny0 = max(by0 - 1, 0), ny1 = min(by1 + 1, GDIM - 1);
        const int nz0 = max(bz0 - 1, 0), nz1 = min(bz1 + 1, GDIM - 1);
        if (nz0 < bz0)
            for (int y = ny0; y <= ny1; y++)
                for (int x = nx0; x <= nx1; x++) PROCCELL(x, y, nz0);
        if (nz1 > bz1)
            for (int y = ny0; y <= ny1; y++)
                for (int x = nx0; x <= nx1; x++) PROCCELL(x, y, nz1);
        for (int z = bz0; z <= bz1; z++) {
            if (ny0 < by0)
                for (int x = nx0; x <= nx1; x++) PROCCELL(x, ny0, z);
            if (ny1 > by1)
                for (int x = nx0; x <= nx1; x++) PROCCELL(x, ny1, z);
            for (int y = by0; y <= by1; y++) {
                if (nx0 < bx0) PROCCELL(nx0, y, z);
                if (nx1 > bx1) PROCCELL(nx1, y, z);
            }
        }
        bx0 = nx0; bx1 = nx1; by0 = ny0; by1 = ny1; bz0 = nz0; bz1 = nz1;
    }
#undef PROCCELL

    // Gather the 5 neighbors by original index; reference numerics.
    const float* basep = pcd + (size_t)b * NPTS * 3;
    const unsigned id0 = (unsigned)h0, id1 = (unsigned)h1, id2 = (unsigned)h2,
                   id3 = (unsigned)h3, id4 = (unsigned)h4;
    float px[KNN], py[KNN], pz[KNN];
    px[0] = basep[id0 * 3 + 0]; py[0] = basep[id0 * 3 + 1]; pz[0] = basep[id0 * 3 + 2];
    px[1] = basep[id1 * 3 + 0]; py[1] = basep[id1 * 3 + 1]; pz[1] = basep[id1 * 3 + 2];
    px[2] = basep[id2 * 3 + 0]; py[2] = basep[id2 * 3 + 1]; pz[2] = basep[id2 * 3 + 2];
    px[3] = basep[id3 * 3 + 0]; py[3] = basep[id3 * 3 + 1]; pz[3] = basep[id3 * 3 + 2];
    px[4] = basep[id4 * 3 + 0]; py[4] = basep[id4 * 3 + 1]; pz[4] = basep[id4 * 3 + 2];

    const float inv_k = 1.0f / (float)KNN;
    float mx = (px[0] + px[1] + px[2] + px[3] + px[4]) * inv_k;
    float my = (py[0] + py[1] + py[2] + py[3] + py[4]) * inv_k;
    float mz = (pz[0] + pz[1] + pz[2] + pz[3] + pz[4]) * inv_k;

    float tr = 0.0f;
#pragma unroll
    for (int c = 0; c < KNN; c++) {
        float dx = px[c] - mx, dy = py[c] - my, dz = pz[c] - mz;
        tr = fmaf(dx, dx, fmaf(dy, dy, fmaf(dz, dz, tr)));
    }
    tr *= 1.0f / (float)(KNN - 1);
    out[b * NPTS + oi] = tr;
}

// --------------------------------------------------------------------------
// K3: deterministic per-CTA partial sums of traces (original index order).
// --------------------------------------------------------------------------
__global__ __launch_bounds__(256) void psum_kernel(const float* __restrict__ out)
{
    __shared__ float warp_sums[8];
    const int t = blockIdx.x * 256 + threadIdx.x;
    float s = out[t];
#pragma unroll
    for (int off = 16; off > 0; off >>= 1)
        s += __shfl_down_sync(0xffffffffu, s, off);
    if ((threadIdx.x & 31) == 0) warp_sums[threadIdx.x >> 5] = s;
    __syncthreads();
    if (threadIdx.x < 32) {
        float v = (threadIdx.x < 8) ? warp_sums[threadIdx.x] : 0.0f;
#pragma unroll
        for (int off = 4; off > 0; off >>= 1)
            v += __shfl_down_sync(0xffffffffu, v, off);
        if (threadIdx.x == 0) g_partial[blockIdx.x] = v;
    }
}

// --------------------------------------------------------------------------
// K4: normalize. 4 CTAs per batch; each redundantly sums its batch's 16
// partials with a fixed-order tree (deterministic) and scales its quarter.
// --------------------------------------------------------------------------
__global__ __launch_bounds__(256) void finalize_kernel(float* __restrict__ out)
{
    __shared__ float s_inv;
    const int b = blockIdx.x >> 2;
    const int quarter = blockIdx.x & 3;

    if (threadIdx.x < 32) {
        float v = (threadIdx.x < 16) ? g_partial[b * 16 + threadIdx.x] : 0.0f;
#pragma unroll
        for (int off = 8; off > 0; off >>= 1)
            v += __shfl_down_sync(0xffffffffu, v, off);
        if (threadIdx.x == 0) s_inv = 1.0f / (v + 1e-8f);
    }
    __syncthreads();

    const float inv = s_inv;
    float* o = out + (size_t)b * NPTS + quarter * (NPTS / 4);
#pragma unroll
    for (int i = 0; i < (NPTS / 4) / 256; i++)
        o[i * 256 + threadIdx.x] *= inv;
}

extern "C" void kernel_launch(void* const* d_in, const int* in_sizes, int n_in,
                              void* d_out, int out_size)
{
    const float* pcd = (const float*)d_in[0];
    float* out = (float*)d_out;

    static bool attr_set = false;  // idempotent host-side attribute
    const int smemq = NPTS * 16 + (GC + 1) * 4;   // ~66 KB
    if (!attr_set) {
        cudaFuncSetAttribute(query_kernel,
                             cudaFuncAttributeMaxDynamicSharedMemorySize, smemq);
        attr_set = true;
    }

    build_kernel<<<NB, 1024>>>(pcd);
    query_kernel<<<NB * 32, QTPB, smemq>>>(pcd, out);
    psum_kernel<<<(NB * NPTS) / 256, 256>>>(out);
    finalize_kernel<<<NB * 4, 256>>>(out);
}